// round 3
// baseline (speedup 1.0000x reference)
#include <cuda_runtime.h>
#include <cstdint>
#include <cstddef>

// Problem dims
#define T_   256
#define B_   64
#define E_   768
#define H_   512
#define H2_  1024
#define G4_  2048
#define MTB  16384   // T_*B_

// ---------------- scratch (static device allocations: allowed) ----------------
__device__ float g_pre_f[(size_t)MTB * G4_];     // 128 MB
__device__ float g_pre_b[(size_t)MTB * G4_];     // 128 MB
__device__ float g_h[2][2][T_ * H_];             // [dir][buf][t*H+k]
__device__ float g_c[2][T_ * H_];                // [dir][t*H+j]
__device__ float g_sents[(size_t)MTB * H2_];     // 64 MB  (t,b,h2)
__device__ float g_mean[B_ * H2_];
__device__ float g_doc[B_ * H2_];
__device__ float g_v[B_ * H2_];
__device__ float g_s0[B_ * T_];
__device__ float g_Wt[H2_ * H2_];                // W_nov transposed
__device__ float g_U[(size_t)MTB * H2_];         // 64 MB

__device__ __forceinline__ float sigm(float x) { return 1.0f / (1.0f + expf(-x)); }

// ---------------- zero LSTM state (every launch / graph replay) ----------------
__global__ void zero_state_k() {
    int i = blockIdx.x * blockDim.x + threadIdx.x;
    if (i < T_ * H_) {
        g_h[0][0][i] = 0.0f; g_h[1][0][i] = 0.0f;
        g_c[0][i]    = 0.0f; g_c[1][i]    = 0.0f;
    }
}

// ---------------- generic SGEMM: C(MxN) = A(MxK) @ W(NxK)^T (+bias) ----------------
// 128x128x8 tile, 256 threads, 8x8 register tile, reg-prefetch double buffer.
__global__ __launch_bounds__(256) void sgemm_nt(
    const float* __restrict__ A, const float* __restrict__ W,
    const float* __restrict__ bias, float* __restrict__ C,
    int M, int N, int K)
{
    __shared__ float As[2][8][132];
    __shared__ float Bs[2][8][132];
    const int tid = threadIdx.x;
    const int lr  = tid >> 1;            // 0..127
    const int lc  = (tid & 1) << 2;      // 0 or 4
    const int tx  = tid & 15;
    const int ty  = tid >> 4;

    const float* Ab = A + (size_t)blockIdx.y * 128 * K;
    const float* Wb = W + (size_t)blockIdx.x * 128 * K;

    float acc[8][8];
#pragma unroll
    for (int i = 0; i < 8; i++)
#pragma unroll
        for (int j = 0; j < 8; j++) acc[i][j] = 0.0f;

    // preload k-block 0
    {
        float4 a4 = *(const float4*)(Ab + (size_t)lr * K + lc);
        float4 b4 = *(const float4*)(Wb + (size_t)lr * K + lc);
        As[0][lc + 0][lr] = a4.x; As[0][lc + 1][lr] = a4.y;
        As[0][lc + 2][lr] = a4.z; As[0][lc + 3][lr] = a4.w;
        Bs[0][lc + 0][lr] = b4.x; Bs[0][lc + 1][lr] = b4.y;
        Bs[0][lc + 2][lr] = b4.z; Bs[0][lc + 3][lr] = b4.w;
    }
    __syncthreads();

    const int nkb = K >> 3;
    for (int kb = 0; kb < nkb; ++kb) {
        const int buf = kb & 1;
        float4 na, nb;
        const bool has = (kb + 1 < nkb);
        if (has) {
            na = *(const float4*)(Ab + (size_t)lr * K + (size_t)(kb + 1) * 8 + lc);
            nb = *(const float4*)(Wb + (size_t)lr * K + (size_t)(kb + 1) * 8 + lc);
        }
#pragma unroll
        for (int k = 0; k < 8; k++) {
            float a[8], b[8];
            *(float4*)(a)     = *(const float4*)&As[buf][k][ty * 8];
            *(float4*)(a + 4) = *(const float4*)&As[buf][k][ty * 8 + 4];
            *(float4*)(b)     = *(const float4*)&Bs[buf][k][tx * 8];
            *(float4*)(b + 4) = *(const float4*)&Bs[buf][k][tx * 8 + 4];
#pragma unroll
            for (int i = 0; i < 8; i++)
#pragma unroll
                for (int j = 0; j < 8; j++) acc[i][j] += a[i] * b[j];
        }
        if (has) {
            const int nbuf = buf ^ 1;
            As[nbuf][lc + 0][lr] = na.x; As[nbuf][lc + 1][lr] = na.y;
            As[nbuf][lc + 2][lr] = na.z; As[nbuf][lc + 3][lr] = na.w;
            Bs[nbuf][lc + 0][lr] = nb.x; Bs[nbuf][lc + 1][lr] = nb.y;
            Bs[nbuf][lc + 2][lr] = nb.z; Bs[nbuf][lc + 3][lr] = nb.w;
        }
        __syncthreads();
    }

    const int n0 = blockIdx.x * 128 + tx * 8;
    float bv[8];
#pragma unroll
    for (int j = 0; j < 8; j++) bv[j] = bias ? bias[n0 + j] : 0.0f;
#pragma unroll
    for (int i = 0; i < 8; i++) {
        float* Crow = C + (size_t)(blockIdx.y * 128 + ty * 8 + i) * N + n0;
        float4 o0, o1;
        o0.x = acc[i][0] + bv[0]; o0.y = acc[i][1] + bv[1];
        o0.z = acc[i][2] + bv[2]; o0.w = acc[i][3] + bv[3];
        o1.x = acc[i][4] + bv[4]; o1.y = acc[i][5] + bv[5];
        o1.z = acc[i][6] + bv[6]; o1.w = acc[i][7] + bv[7];
        *(float4*)(Crow)     = o0;
        *(float4*)(Crow + 4) = o1;
    }
}

// ---------------- LSTM step s (both directions, fused GEMM + gate update) -------
// Grid 128: bid>>6 = dir, (bid&63): 2 m-tiles (128 rows of t) x 32 j-slices (16 j).
// CTA columns = 16 j's x 4 gates (each thread owns the full i/f/g/o quadruple).
__global__ __launch_bounds__(256) void lstm_step(
    int s, const float* __restrict__ w_hh_f, const float* __restrict__ w_hh_b)
{
    __shared__ float Hs[2][8][132];
    __shared__ float Ws[2][8][68];
    const int tid  = threadIdx.x;
    const int bidx = blockIdx.x;
    const int dir  = bidx >> 6;
    const int r    = bidx & 63;
    const int m0   = (r >> 5) * 128;
    const int j0   = (r & 31) * 16;

    const float* Wh  = dir ? w_hh_b : w_hh_f;
    const float* PRE = dir ? g_pre_b : g_pre_f;
    const float* Hin = g_h[dir][s & 1];
    float* Hout      = g_h[dir][(s & 1) ^ 1];
    float* Cst       = g_c[dir];
    const int bb     = dir ? (63 - s) : s;

    const int lr  = tid >> 1;            // 0..127 (H rows)
    const int lc  = (tid & 1) << 2;
    const int wr  = tid >> 1;            // 0..63 valid when tid<128 (W cols)
    const int wg  = (wr & 3) * 512 + j0 + (wr >> 2);   // gate-major row index
    const int tx  = tid & 15;            // j within slice
    const int ty  = tid >> 4;            // row group

    float acc[8][4];
#pragma unroll
    for (int i = 0; i < 8; i++)
#pragma unroll
        for (int j = 0; j < 4; j++) acc[i][j] = 0.0f;

    {
        float4 a4 = *(const float4*)(Hin + (size_t)(m0 + lr) * H_ + lc);
        Hs[0][lc + 0][lr] = a4.x; Hs[0][lc + 1][lr] = a4.y;
        Hs[0][lc + 2][lr] = a4.z; Hs[0][lc + 3][lr] = a4.w;
        if (tid < 128) {
            float4 w4 = *(const float4*)(Wh + (size_t)wg * H_ + lc);
            Ws[0][lc + 0][wr] = w4.x; Ws[0][lc + 1][wr] = w4.y;
            Ws[0][lc + 2][wr] = w4.z; Ws[0][lc + 3][wr] = w4.w;
        }
    }
    __syncthreads();

    const int nkb = H_ >> 3;   // 64
    for (int kb = 0; kb < nkb; ++kb) {
        const int buf = kb & 1;
        float4 na, nw;
        const bool has = (kb + 1 < nkb);
        if (has) {
            na = *(const float4*)(Hin + (size_t)(m0 + lr) * H_ + (size_t)(kb + 1) * 8 + lc);
            if (tid < 128)
                nw = *(const float4*)(Wh + (size_t)wg * H_ + (size_t)(kb + 1) * 8 + lc);
        }
#pragma unroll
        for (int k = 0; k < 8; k++) {
            float a[8], b[4];
            *(float4*)(a)     = *(const float4*)&Hs[buf][k][ty * 8];
            *(float4*)(a + 4) = *(const float4*)&Hs[buf][k][ty * 8 + 4];
            *(float4*)(b)     = *(const float4*)&Ws[buf][k][tx * 4];
#pragma unroll
            for (int i = 0; i < 8; i++)
#pragma unroll
                for (int j = 0; j < 4; j++) acc[i][j] += a[i] * b[j];
        }
        if (has) {
            const int nbuf = buf ^ 1;
            Hs[nbuf][lc + 0][lr] = na.x; Hs[nbuf][lc + 1][lr] = na.y;
            Hs[nbuf][lc + 2][lr] = na.z; Hs[nbuf][lc + 3][lr] = na.w;
            if (tid < 128) {
                Ws[nbuf][lc + 0][wr] = nw.x; Ws[nbuf][lc + 1][wr] = nw.y;
                Ws[nbuf][lc + 2][wr] = nw.z; Ws[nbuf][lc + 3][wr] = nw.w;
            }
        }
        __syncthreads();
    }

    // epilogue: add pre, apply LSTM cell, write c/h/sents
    const int j = j0 + tx;
#pragma unroll
    for (int i = 0; i < 8; i++) {
        const int m = m0 + ty * 8 + i;                       // t index
        const size_t pb = ((size_t)m * B_ + bb) * (size_t)G4_;
        float gi_ = acc[i][0] + PRE[pb + 0 * 512 + j];
        float gf_ = acc[i][1] + PRE[pb + 1 * 512 + j];
        float gg_ = acc[i][2] + PRE[pb + 2 * 512 + j];
        float go_ = acc[i][3] + PRE[pb + 3 * 512 + j];
        float cprev = Cst[m * H_ + j];
        float cnew  = sigm(gf_) * cprev + sigm(gi_) * tanhf(gg_);
        float hnew  = sigm(go_) * tanhf(cnew);
        Cst[m * H_ + j]  = cnew;
        Hout[m * H_ + j] = hnew;
        g_sents[((size_t)m * B_ + bb) * (size_t)H2_ + (size_t)dir * H_ + j] = hnew;
    }
}

// ---------------- mean over t of sents -> (B, H2) ----------------
__global__ void col_mean_k() {
    int idx = blockIdx.x * 256 + threadIdx.x;   // b*1024 + h, < 65536
    float sum = 0.0f;
    for (int t = 0; t < T_; t++) sum += g_sents[(size_t)t * (B_ * H2_) + idx];
    g_mean[idx] = sum * (1.0f / 256.0f);
}

// ---------------- small GEMM, warp per output: out(64xN) = X(64xK) @ W(NxK)^T --
__global__ void wdot_gemm(const float* __restrict__ X, const float* __restrict__ W,
                          const float* __restrict__ bias, float* __restrict__ out,
                          int N, int K, int act)
{
    int gw   = (blockIdx.x * blockDim.x + threadIdx.x) >> 5;
    int lane = threadIdx.x & 31;
    int b = gw / N, n = gw % N;
    const float* xr = X + (size_t)b * K;
    const float* wr = W + (size_t)n * K;
    float s = 0.0f;
    for (int k = lane * 4; k < K; k += 128) {
        float4 xv = *(const float4*)(xr + k);
        float4 wv = *(const float4*)(wr + k);
        s += xv.x * wv.x + xv.y * wv.y + xv.z * wv.z + xv.w * wv.w;
    }
#pragma unroll
    for (int off = 16; off; off >>= 1) s += __shfl_xor_sync(0xffffffffu, s, off);
    if (lane == 0) {
        float rr = s + (bias ? bias[n] : 0.0f);
        if (act) rr = tanhf(rr);
        out[(size_t)b * N + n] = rr;
    }
}

// ---------------- s0[b,t] = cont + sal + abs_p[t] + bias ----------------
__global__ void s0_kernel(const float* __restrict__ w_content,
                          const float* __restrict__ pos_emb,
                          const float* __restrict__ w_abs,
                          const float* __restrict__ biasp)
{
    int gw   = (blockIdx.x * blockDim.x + threadIdx.x) >> 5;   // 0..16383
    int lane = threadIdx.x & 31;
    int b = gw >> 8, t = gw & 255;
    const float* hr = g_sents + ((size_t)t * B_ + b) * (size_t)H2_;
    const float* vr = g_v + (size_t)b * H2_;
    float s = 0.0f;
    for (int k = lane * 4; k < H2_; k += 128) {
        float4 hv = *(const float4*)(hr + k);
        float4 wc = *(const float4*)(w_content + k);
        float4 vv = *(const float4*)(vr + k);
        s += hv.x * (wc.x + vv.x) + hv.y * (wc.y + vv.y)
           + hv.z * (wc.z + vv.z) + hv.w * (wc.w + vv.w);
    }
    for (int p = lane; p < 100; p += 32) s += pos_emb[t * 100 + p] * w_abs[p];
#pragma unroll
    for (int off = 16; off; off >>= 1) s += __shfl_xor_sync(0xffffffffu, s, off);
    if (lane == 0) g_s0[b * T_ + t] = s + biasp[0];
}

// ---------------- 1024x1024 transpose: g_Wt[n][h] = W_nov[h][n] ----------------
__global__ void transpose_sq(const float* __restrict__ src, float* __restrict__ dst) {
    __shared__ float tile[32][33];
    int x = blockIdx.x * 32 + threadIdx.x;
    int y = blockIdx.y * 32 + threadIdx.y;
#pragma unroll
    for (int j = 0; j < 32; j += 8)
        tile[threadIdx.y + j][threadIdx.x] = src[(size_t)(y + j) * H2_ + x];
    __syncthreads();
    x = blockIdx.y * 32 + threadIdx.x;
    y = blockIdx.x * 32 + threadIdx.y;
#pragma unroll
    for (int j = 0; j < 32; j += 8)
        dst[(size_t)(y + j) * H2_ + x] = tile[threadIdx.x][threadIdx.y + j];
}

// ---------------- novelty scan: 64 independent CTAs (one per batch) ------------
__global__ __launch_bounds__(256) void nov_scan(float* __restrict__ out) {
    __shared__ float summ[H2_];
    __shared__ float red[8];
    __shared__ float prsh;
    const int b = blockIdx.x, tid = threadIdx.x;
    const int lane = tid & 31, wid = tid >> 5;
#pragma unroll
    for (int i = 0; i < 4; i++) summ[tid + i * 256] = 0.0f;
    __syncthreads();
    for (int t = 0; t < T_; t++) {
        const float* Ur = g_U + ((size_t)t * B_ + b) * (size_t)H2_;
        float p = 0.0f;
#pragma unroll
        for (int i = 0; i < 4; i++) {
            int k = tid + i * 256;
            p += Ur[k] * tanhf(summ[k]);
        }
#pragma unroll
        for (int off = 16; off; off >>= 1) p += __shfl_xor_sync(0xffffffffu, p, off);
        if (lane == 0) red[wid] = p;
        __syncthreads();
        if (tid == 0) {
            float nov = red[0] + red[1] + red[2] + red[3]
                      + red[4] + red[5] + red[6] + red[7];
            float pr = 1.0f / (1.0f + expf(-(g_s0[b * T_ + t] - nov)));
            prsh = pr;
            out[b * T_ + t] = pr;
        }
        __syncthreads();
        float pr = prsh;
        const float* hr = g_sents + ((size_t)t * B_ + b) * (size_t)H2_;
#pragma unroll
        for (int i = 0; i < 4; i++) {
            int k = tid + i * 256;
            summ[k] += pr * hr[k];
        }
        __syncthreads();
    }
}

// ---------------- host ----------------
extern "C" void kernel_launch(void* const* d_in, const int* in_sizes, int n_in,
                              void* d_out, int out_size) {
    (void)in_sizes; (void)n_in; (void)out_size;
    const float* emb       = (const float*)d_in[0];
    const float* w_ih_f    = (const float*)d_in[2];
    const float* w_hh_f    = (const float*)d_in[3];
    const float* b_f       = (const float*)d_in[4];
    const float* w_ih_b    = (const float*)d_in[5];
    const float* w_hh_b    = (const float*)d_in[6];
    const float* b_b       = (const float*)d_in[7];
    const float* W_fdoc    = (const float*)d_in[8];
    const float* b_fdoc    = (const float*)d_in[9];
    const float* pos_emb   = (const float*)d_in[10];
    const float* w_content = (const float*)d_in[11];
    const float* W_sal     = (const float*)d_in[12];
    const float* W_nov     = (const float*)d_in[13];
    const float* w_abs     = (const float*)d_in[14];
    const float* biasp     = (const float*)d_in[15];
    float* out = (float*)d_out;

    float *pre_f, *pre_b, *sents, *mean, *doc, *v, *Wt, *U;
    cudaGetSymbolAddress((void**)&pre_f, g_pre_f);
    cudaGetSymbolAddress((void**)&pre_b, g_pre_b);
    cudaGetSymbolAddress((void**)&sents, g_sents);
    cudaGetSymbolAddress((void**)&mean,  g_mean);
    cudaGetSymbolAddress((void**)&doc,   g_doc);
    cudaGetSymbolAddress((void**)&v,     g_v);
    cudaGetSymbolAddress((void**)&Wt,    g_Wt);
    cudaGetSymbolAddress((void**)&U,     g_U);

    zero_state_k<<<(T_ * H_ + 255) / 256, 256>>>();
    transpose_sq<<<dim3(32, 32), dim3(32, 8)>>>(W_nov, Wt);

    // pre[t*64+b][g] = emb @ w_ih^T + b   (M=16384, N=2048, K=768)
    sgemm_nt<<<dim3(G4_ / 128, MTB / 128), 256>>>(emb, w_ih_f, b_f, pre_f, MTB, G4_, E_);
    sgemm_nt<<<dim3(G4_ / 128, MTB / 128), 256>>>(emb, w_ih_b, b_b, pre_b, MTB, G4_, E_);

    // 64 sequential LSTM steps (over batch axis; fwd + bwd fused per step)
    for (int s = 0; s < 64; s++) lstm_step<<<128, 256>>>(s, w_hh_f, w_hh_b);

    col_mean_k<<<B_ * H2_ / 256, 256>>>();
    // doc = tanh(mean @ W_fdoc^T + b_fdoc)
    wdot_gemm<<<(B_ * H2_) * 32 / 256, 256>>>(mean, W_fdoc, b_fdoc, doc, H2_, H2_, 1);
    // v = doc @ W_sal^T
    wdot_gemm<<<(B_ * H2_) * 32 / 256, 256>>>(doc, W_sal, nullptr, v, H2_, H2_, 0);

    s0_kernel<<<(B_ * T_) * 32 / 256, 256>>>(w_content, pos_emb, w_abs, biasp);

    // U[t*64+b][k] = sents @ W_nov   (via W_nov^T,  M=16384, N=1024, K=1024)
    sgemm_nt<<<dim3(H2_ / 128, MTB / 128), 256>>>(sents, Wt, nullptr, U, MTB, H2_, H2_);

    nov_scan<<<B_, 256>>>(out);
}

// round 5
// speedup vs baseline: 2.1130x; 2.1130x over previous
#include <cuda_runtime.h>
#include <cuda_bf16.h>
#include <cstdint>
#include <cstddef>

// Problem dims
#define T_   256
#define B_   64
#define E_   768
#define H_   512
#define H2_  1024
#define G4_  2048
#define G8_  4096
#define MTB  16384   // T_*B_

// ============================ scratch ============================
__device__ float g_pre[(size_t)MTB * G8_];        // [m][dir*2048 + gate*512 + j]
__device__ float g_h[2][2][T_ * H_];
__device__ float g_c[2][T_ * H_];
__device__ float g_sents[(size_t)MTB * H2_];
__device__ __nv_bfloat16 g_sents_hi[(size_t)MTB * H2_];
__device__ __nv_bfloat16 g_sents_lo[(size_t)MTB * H2_];
__device__ __nv_bfloat16 g_emb_hi[(size_t)MTB * E_];
__device__ __nv_bfloat16 g_emb_lo[(size_t)MTB * E_];
__device__ __nv_bfloat16 g_wih_hi[(size_t)G8_ * E_];   // cat [w_ih_f; w_ih_b]
__device__ __nv_bfloat16 g_wih_lo[(size_t)G8_ * E_];
__device__ float g_bias4[G8_];
__device__ float g_Wt[H2_ * H2_];
__device__ __nv_bfloat16 g_Wt_hi[H2_ * H2_];
__device__ __nv_bfloat16 g_Wt_lo[H2_ * H2_];
__device__ float g_mean[B_ * H2_];
__device__ float g_doc[B_ * H2_];
__device__ float g_v[B_ * H2_];
__device__ float g_s0[B_ * T_];
__device__ float g_U[(size_t)MTB * H2_];

__device__ __forceinline__ float sigm(float x) { return 1.0f / (1.0f + expf(-x)); }

__device__ __forceinline__ uint32_t smem_u32(const void* p) {
    uint32_t a;
    asm("{ .reg .u64 t; cvta.to.shared.u64 t, %1; cvt.u32.u64 %0, t; }" : "=r"(a) : "l"(p));
    return a;
}
__device__ __forceinline__ uint32_t lds32(uint32_t a) {
    uint32_t v; asm("ld.shared.b32 %0, [%1];" : "=r"(v) : "r"(a)); return v;
}
__device__ __forceinline__ void cp16(uint32_t dst, const void* src) {
    asm volatile("cp.async.cg.shared.global [%0], [%1], 16;" :: "r"(dst), "l"(src));
}
#define CP_COMMIT() asm volatile("cp.async.commit_group;" ::: "memory")
#define CP_WAIT(n)  asm volatile("cp.async.wait_group %0;" :: "n"(n) : "memory")

__device__ __forceinline__ void mma_bf16(float* c, uint32_t a0, uint32_t a1,
                                         uint32_t a2, uint32_t a3,
                                         uint32_t b0, uint32_t b1) {
    asm("mma.sync.aligned.m16n8k16.row.col.f32.bf16.bf16.f32 "
        "{%0,%1,%2,%3}, {%4,%5,%6,%7}, {%8,%9}, {%0,%1,%2,%3};"
        : "+f"(c[0]), "+f"(c[1]), "+f"(c[2]), "+f"(c[3])
        : "r"(a0), "r"(a1), "r"(a2), "r"(a3), "r"(b0), "r"(b1));
}

// ============================ prep kernels ============================
__global__ void zero_state_k() {
    int i = blockIdx.x * blockDim.x + threadIdx.x;
    if (i < T_ * H_) {
        g_h[0][0][i] = 0.0f; g_h[1][0][i] = 0.0f;
        g_c[0][i]    = 0.0f; g_c[1][i]    = 0.0f;
    }
}

__global__ void split_bf16_k(const float* __restrict__ src,
                             __nv_bfloat16* __restrict__ hi,
                             __nv_bfloat16* __restrict__ lo, int n) {
    int i = blockIdx.x * 256 + threadIdx.x;
    if (i < n) {
        float x = src[i];
        __nv_bfloat16 h = __float2bfloat16(x);
        hi[i] = h;
        lo[i] = __float2bfloat16(x - __bfloat162float(h));
    }
}

__global__ void bias_cat_k(const float* __restrict__ bf, const float* __restrict__ bb) {
    int i = blockIdx.x * 256 + threadIdx.x;
    if (i < G4_) { g_bias4[i] = bf[i]; g_bias4[i + G4_] = bb[i]; }
}

__global__ void transpose_sq(const float* __restrict__ src, float* __restrict__ dst) {
    __shared__ float tile[32][33];
    int x = blockIdx.x * 32 + threadIdx.x;
    int y = blockIdx.y * 32 + threadIdx.y;
#pragma unroll
    for (int j = 0; j < 32; j += 8)
        tile[threadIdx.y + j][threadIdx.x] = src[(size_t)(y + j) * H2_ + x];
    __syncthreads();
    x = blockIdx.y * 32 + threadIdx.x;
    y = blockIdx.x * 32 + threadIdx.y;
#pragma unroll
    for (int j = 0; j < 32; j += 8)
        dst[(size_t)(y + j) * H2_ + x] = tile[threadIdx.x][threadIdx.y + j];
}

// ==================== mma.sync split-bf16 GEMM ====================
// C[M][N] = A(M,K) @ B(N,K)^T (+bias), A/B given as hi/lo bf16 pairs.
// 128x128 tile, BK=32, 8 warps (2x4), warp tile 64x32, cp.async 2-stage.
// smem tile: 128 rows x 80B (32 bf16 data + 8 pad) -> conflict-free lds.
#define TROW    80
#define TILE_SZ (128 * TROW)          // 10240 B
#define STAGE_SZ (4 * TILE_SZ)        // 40960 B (Ah, Al, Bh, Bl)
#define GSMEM   (2 * STAGE_SZ)        // 81920 B

__global__ __launch_bounds__(256, 1) void gemm_mma(
    const __nv_bfloat16* __restrict__ Ah, const __nv_bfloat16* __restrict__ Al,
    const __nv_bfloat16* __restrict__ Bh, const __nv_bfloat16* __restrict__ Bl,
    const float* __restrict__ bias, float* __restrict__ C, int K, int N_ld)
{
    extern __shared__ char dsm[];
    const uint32_t sb = smem_u32(dsm);
    const int tid  = threadIdx.x;
    const int wid  = tid >> 5, lane = tid & 31;
    const int t4   = lane >> 2, tm4 = lane & 3;
    const int m0   = blockIdx.y * 128;
    const int n0   = blockIdx.x * 128;
    const int wm   = (wid >> 2) * 64;     // warp m offset
    const int wn   = (wid & 3) * 32;      // warp n offset

    const char* srcs[4];
    srcs[0] = (const char*)Ah + (size_t)m0 * K * 2;
    srcs[1] = (const char*)Al + (size_t)m0 * K * 2;
    srcs[2] = (const char*)Bh + (size_t)n0 * K * 2;
    srcs[3] = (const char*)Bl + (size_t)n0 * K * 2;
    const size_t rstride = (size_t)K * 2;

    // cp.async per-thread mapping: 2 chunks of 16B per tile
    const int prow0 = tid >> 2,        pq0 = tid & 3;         // u = tid
    const int prow1 = (tid + 256) >> 2, pq1 = (tid + 256) & 3; // u = tid+256

    const int NC = K >> 5;  // K chunks of 32 bf16 (64B rows)

#define PREFETCH(c, s) do {                                                     \
    const uint32_t stg = sb + (s) * STAGE_SZ;                                   \
    _Pragma("unroll")                                                           \
    for (int t = 0; t < 4; t++) {                                               \
        cp16(stg + t * TILE_SZ + prow0 * TROW + pq0 * 16,                       \
             srcs[t] + (size_t)prow0 * rstride + (size_t)(c) * 64 + pq0 * 16);  \
        cp16(stg + t * TILE_SZ + prow1 * TROW + pq1 * 16,                       \
             srcs[t] + (size_t)prow1 * rstride + (size_t)(c) * 64 + pq1 * 16);  \
    } } while (0)

    float acc[4][4][4];
#pragma unroll
    for (int mi = 0; mi < 4; mi++)
#pragma unroll
        for (int ni = 0; ni < 4; ni++)
#pragma unroll
            for (int k = 0; k < 4; k++) acc[mi][ni][k] = 0.0f;

    PREFETCH(0, 0); CP_COMMIT();
    if (NC > 1) { PREFETCH(1, 1); CP_COMMIT(); }

    for (int c = 0; c < NC; c++) {
        if (c + 1 < NC) { CP_WAIT(1); } else { CP_WAIT(0); }
        __syncthreads();

        const uint32_t stg = sb + (c & 1) * STAGE_SZ;
        const uint32_t pAh = stg;
        const uint32_t pAl = stg + TILE_SZ;
        const uint32_t pBh = stg + 2 * TILE_SZ;
        const uint32_t pBl = stg + 3 * TILE_SZ;

#pragma unroll
        for (int ks = 0; ks < 2; ks++) {
            const uint32_t koff = ks * 32 + tm4 * 4;   // bytes within row
            uint32_t ah[4][4], al[4][4], bh[4][2], bl[4][2];
#pragma unroll
            for (int mi = 0; mi < 4; mi++) {
                uint32_t base = pAh + (uint32_t)(wm + mi * 16 + t4) * TROW + koff;
                ah[mi][0] = lds32(base);
                ah[mi][1] = lds32(base + 8 * TROW);
                ah[mi][2] = lds32(base + 16);
                ah[mi][3] = lds32(base + 8 * TROW + 16);
            }
#pragma unroll
            for (int ni = 0; ni < 4; ni++) {
                uint32_t base = pBh + (uint32_t)(wn + ni * 8 + t4) * TROW + koff;
                bh[ni][0] = lds32(base);
                bh[ni][1] = lds32(base + 16);
            }
#pragma unroll
            for (int mi = 0; mi < 4; mi++)
#pragma unroll
                for (int ni = 0; ni < 4; ni++)
                    mma_bf16(acc[mi][ni], ah[mi][0], ah[mi][1], ah[mi][2], ah[mi][3],
                             bh[ni][0], bh[ni][1]);
#pragma unroll
            for (int ni = 0; ni < 4; ni++) {
                uint32_t base = pBl + (uint32_t)(wn + ni * 8 + t4) * TROW + koff;
                bl[ni][0] = lds32(base);
                bl[ni][1] = lds32(base + 16);
            }
#pragma unroll
            for (int mi = 0; mi < 4; mi++)
#pragma unroll
                for (int ni = 0; ni < 4; ni++)
                    mma_bf16(acc[mi][ni], ah[mi][0], ah[mi][1], ah[mi][2], ah[mi][3],
                             bl[ni][0], bl[ni][1]);
#pragma unroll
            for (int mi = 0; mi < 4; mi++) {
                uint32_t base = pAl + (uint32_t)(wm + mi * 16 + t4) * TROW + koff;
                al[mi][0] = lds32(base);
                al[mi][1] = lds32(base + 8 * TROW);
                al[mi][2] = lds32(base + 16);
                al[mi][3] = lds32(base + 8 * TROW + 16);
            }
#pragma unroll
            for (int mi = 0; mi < 4; mi++)
#pragma unroll
                for (int ni = 0; ni < 4; ni++)
                    mma_bf16(acc[mi][ni], al[mi][0], al[mi][1], al[mi][2], al[mi][3],
                             bh[ni][0], bh[ni][1]);
        }
        __syncthreads();
        if (c + 2 < NC) { PREFETCH(c + 2, c & 1); CP_COMMIT(); }
    }
#undef PREFETCH

    // epilogue
#pragma unroll
    for (int mi = 0; mi < 4; mi++) {
        const int r0 = m0 + wm + mi * 16 + t4;
#pragma unroll
        for (int ni = 0; ni < 4; ni++) {
            const int col = n0 + wn + ni * 8 + 2 * tm4;
            float b0 = bias ? bias[col] : 0.0f;
            float b1 = bias ? bias[col + 1] : 0.0f;
            float2 v0 = { acc[mi][ni][0] + b0, acc[mi][ni][1] + b1 };
            float2 v1 = { acc[mi][ni][2] + b0, acc[mi][ni][3] + b1 };
            *(float2*)(C + (size_t)r0 * N_ld + col)       = v0;
            *(float2*)(C + (size_t)(r0 + 8) * N_ld + col) = v1;
        }
    }
}

// ==================== LSTM step (fp32, fused GEMM + gates) ====================
__global__ __launch_bounds__(256) void lstm_step(
    int s, const float* __restrict__ w_hh_f, const float* __restrict__ w_hh_b)
{
    __shared__ float Hs[2][8][132];
    __shared__ float Ws[2][8][68];
    const int tid  = threadIdx.x;
    const int bidx = blockIdx.x;
    const int dir  = bidx >> 6;
    const int r    = bidx & 63;
    const int m0   = (r >> 5) * 128;
    const int j0   = (r & 31) * 16;

    const float* Wh  = dir ? w_hh_b : w_hh_f;
    const float* Hin = g_h[dir][s & 1];
    float* Hout      = g_h[dir][(s & 1) ^ 1];
    float* Cst       = g_c[dir];
    const int bb     = dir ? (63 - s) : s;

    const int lr  = tid >> 1;
    const int lc  = (tid & 1) << 2;
    const int wr  = tid >> 1;
    const int wg  = (wr & 3) * 512 + j0 + (wr >> 2);
    const int tx  = tid & 15;
    const int ty  = tid >> 4;

    float acc[8][4];
#pragma unroll
    for (int i = 0; i < 8; i++)
#pragma unroll
        for (int j = 0; j < 4; j++) acc[i][j] = 0.0f;

    {
        float4 a4 = *(const float4*)(Hin + (size_t)(m0 + lr) * H_ + lc);
        Hs[0][lc + 0][lr] = a4.x; Hs[0][lc + 1][lr] = a4.y;
        Hs[0][lc + 2][lr] = a4.z; Hs[0][lc + 3][lr] = a4.w;
        if (tid < 128) {
            float4 w4 = *(const float4*)(Wh + (size_t)wg * H_ + lc);
            Ws[0][lc + 0][wr] = w4.x; Ws[0][lc + 1][wr] = w4.y;
            Ws[0][lc + 2][wr] = w4.z; Ws[0][lc + 3][wr] = w4.w;
        }
    }
    __syncthreads();

    const int nkb = H_ >> 3;
    for (int kb = 0; kb < nkb; ++kb) {
        const int buf = kb & 1;
        float4 na, nw;
        const bool has = (kb + 1 < nkb);
        if (has) {
            na = *(const float4*)(Hin + (size_t)(m0 + lr) * H_ + (size_t)(kb + 1) * 8 + lc);
            if (tid < 128)
                nw = *(const float4*)(Wh + (size_t)wg * H_ + (size_t)(kb + 1) * 8 + lc);
        }
#pragma unroll
        for (int k = 0; k < 8; k++) {
            float a[8], b[4];
            *(float4*)(a)     = *(const float4*)&Hs[buf][k][ty * 8];
            *(float4*)(a + 4) = *(const float4*)&Hs[buf][k][ty * 8 + 4];
            *(float4*)(b)     = *(const float4*)&Ws[buf][k][tx * 4];
#pragma unroll
            for (int i = 0; i < 8; i++)
#pragma unroll
                for (int j = 0; j < 4; j++) acc[i][j] += a[i] * b[j];
        }
        if (has) {
            const int nbuf = buf ^ 1;
            Hs[nbuf][lc + 0][lr] = na.x; Hs[nbuf][lc + 1][lr] = na.y;
            Hs[nbuf][lc + 2][lr] = na.z; Hs[nbuf][lc + 3][lr] = na.w;
            if (tid < 128) {
                Ws[nbuf][lc + 0][wr] = nw.x; Ws[nbuf][lc + 1][wr] = nw.y;
                Ws[nbuf][lc + 2][wr] = nw.z; Ws[nbuf][lc + 3][wr] = nw.w;
            }
        }
        __syncthreads();
    }

    const int j = j0 + tx;
#pragma unroll
    for (int i = 0; i < 8; i++) {
        const int m = m0 + ty * 8 + i;
        const size_t pb = ((size_t)m * B_ + bb) * (size_t)G8_ + (size_t)dir * G4_;
        float gi_ = acc[i][0] + g_pre[pb + 0 * 512 + j];
        float gf_ = acc[i][1] + g_pre[pb + 1 * 512 + j];
        float gg_ = acc[i][2] + g_pre[pb + 2 * 512 + j];
        float go_ = acc[i][3] + g_pre[pb + 3 * 512 + j];
        float cprev = Cst[m * H_ + j];
        float cnew  = sigm(gf_) * cprev + sigm(gi_) * tanhf(gg_);
        float hnew  = sigm(go_) * tanhf(cnew);
        Cst[m * H_ + j]  = cnew;
        Hout[m * H_ + j] = hnew;
        const size_t si = ((size_t)m * B_ + bb) * (size_t)H2_ + (size_t)dir * H_ + j;
        g_sents[si] = hnew;
        __nv_bfloat16 hh = __float2bfloat16(hnew);
        g_sents_hi[si] = hh;
        g_sents_lo[si] = __float2bfloat16(hnew - __bfloat162float(hh));
    }
}

// ==================== small kernels ====================
__global__ void col_mean_k() {
    int idx = blockIdx.x * 256 + threadIdx.x;
    float sum = 0.0f;
    for (int t = 0; t < T_; t++) sum += g_sents[(size_t)t * (B_ * H2_) + idx];
    g_mean[idx] = sum * (1.0f / 256.0f);
}

__global__ void wdot_gemm(const float* __restrict__ X, const float* __restrict__ W,
                          const float* __restrict__ bias, float* __restrict__ out,
                          int N, int K, int act)
{
    int gw   = (blockIdx.x * blockDim.x + threadIdx.x) >> 5;
    int lane = threadIdx.x & 31;
    int b = gw / N, n = gw % N;
    const float* xr = X + (size_t)b * K;
    const float* wr = W + (size_t)n * K;
    float s = 0.0f;
    for (int k = lane * 4; k < K; k += 128) {
        float4 xv = *(const float4*)(xr + k);
        float4 wv = *(const float4*)(wr + k);
        s += xv.x * wv.x + xv.y * wv.y + xv.z * wv.z + xv.w * wv.w;
    }
#pragma unroll
    for (int off = 16; off; off >>= 1) s += __shfl_xor_sync(0xffffffffu, s, off);
    if (lane == 0) {
        float rr = s + (bias ? bias[n] : 0.0f);
        if (act) rr = tanhf(rr);
        out[(size_t)b * N + n] = rr;
    }
}

__global__ void s0_kernel(const float* __restrict__ w_content,
                          const float* __restrict__ pos_emb,
                          const float* __restrict__ w_abs,
                          const float* __restrict__ biasp)
{
    int gw   = (blockIdx.x * blockDim.x + threadIdx.x) >> 5;
    int lane = threadIdx.x & 31;
    int b = gw >> 8, t = gw & 255;
    const float* hr = g_sents + ((size_t)t * B_ + b) * (size_t)H2_;
    const float* vr = g_v + (size_t)b * H2_;
    float s = 0.0f;
    for (int k = lane * 4; k < H2_; k += 128) {
        float4 hv = *(const float4*)(hr + k);
        float4 wc = *(const float4*)(w_content + k);
        float4 vv = *(const float4*)(vr + k);
        s += hv.x * (wc.x + vv.x) + hv.y * (wc.y + vv.y)
           + hv.z * (wc.z + vv.z) + hv.w * (wc.w + vv.w);
    }
    for (int p = lane; p < 100; p += 32) s += pos_emb[t * 100 + p] * w_abs[p];
#pragma unroll
    for (int off = 16; off; off >>= 1) s += __shfl_xor_sync(0xffffffffu, s, off);
    if (lane == 0) g_s0[b * T_ + t] = s + biasp[0];
}

__global__ __launch_bounds__(256) void nov_scan(float* __restrict__ out) {
    __shared__ float summ[H2_];
    __shared__ float red[8];
    __shared__ float prsh;
    const int b = blockIdx.x, tid = threadIdx.x;
    const int lane = tid & 31, wid = tid >> 5;
#pragma unroll
    for (int i = 0; i < 4; i++) summ[tid + i * 256] = 0.0f;
    __syncthreads();
    for (int t = 0; t < T_; t++) {
        const float* Ur = g_U + ((size_t)t * B_ + b) * (size_t)H2_;
        float p = 0.0f;
#pragma unroll
        for (int i = 0; i < 4; i++) {
            int k = tid + i * 256;
            p += Ur[k] * tanhf(summ[k]);
        }
#pragma unroll
        for (int off = 16; off; off >>= 1) p += __shfl_xor_sync(0xffffffffu, p, off);
        if (lane == 0) red[wid] = p;
        __syncthreads();
        if (tid == 0) {
            float nov = red[0] + red[1] + red[2] + red[3]
                      + red[4] + red[5] + red[6] + red[7];
            float pr = 1.0f / (1.0f + expf(-(g_s0[b * T_ + t] - nov)));
            prsh = pr;
            out[b * T_ + t] = pr;
        }
        __syncthreads();
        float pr = prsh;
        const float* hr = g_sents + ((size_t)t * B_ + b) * (size_t)H2_;
#pragma unroll
        for (int i = 0; i < 4; i++) {
            int k = tid + i * 256;
            summ[k] += pr * hr[k];
        }
        __syncthreads();
    }
}

// ==================== host ====================
extern "C" void kernel_launch(void* const* d_in, const int* in_sizes, int n_in,
                              void* d_out, int out_size) {
    (void)in_sizes; (void)n_in; (void)out_size;
    const float* emb       = (const float*)d_in[0];
    const float* w_ih_f    = (const float*)d_in[2];
    const float* w_hh_f    = (const float*)d_in[3];
    const float* b_f       = (const float*)d_in[4];
    const float* w_ih_b    = (const float*)d_in[5];
    const float* w_hh_b    = (const float*)d_in[6];
    const float* b_b       = (const float*)d_in[7];
    const float* W_fdoc    = (const float*)d_in[8];
    const float* b_fdoc    = (const float*)d_in[9];
    const float* pos_emb   = (const float*)d_in[10];
    const float* w_content = (const float*)d_in[11];
    const float* W_sal     = (const float*)d_in[12];
    const float* W_nov     = (const float*)d_in[13];
    const float* w_abs     = (const float*)d_in[14];
    const float* biasp     = (const float*)d_in[15];
    float* out = (float*)d_out;

    static int smem_set = 0;
    if (!smem_set) {
        cudaFuncSetAttribute(gemm_mma, cudaFuncAttributeMaxDynamicSharedMemorySize, GSMEM);
        smem_set = 1;
    }

    float *pre, *mean, *doc, *v, *Wt, *U, *bias4;
    __nv_bfloat16 *eh, *el, *wh, *wl, *sh, *sl, *wth, *wtl;
    cudaGetSymbolAddress((void**)&pre,   g_pre);
    cudaGetSymbolAddress((void**)&mean,  g_mean);
    cudaGetSymbolAddress((void**)&doc,   g_doc);
    cudaGetSymbolAddress((void**)&v,     g_v);
    cudaGetSymbolAddress((void**)&Wt,    g_Wt);
    cudaGetSymbolAddress((void**)&U,     g_U);
    cudaGetSymbolAddress((void**)&bias4, g_bias4);
    cudaGetSymbolAddress((void**)&eh,  g_emb_hi);
    cudaGetSymbolAddress((void**)&el,  g_emb_lo);
    cudaGetSymbolAddress((void**)&wh,  g_wih_hi);
    cudaGetSymbolAddress((void**)&wl,  g_wih_lo);
    cudaGetSymbolAddress((void**)&sh,  g_sents_hi);
    cudaGetSymbolAddress((void**)&sl,  g_sents_lo);
    cudaGetSymbolAddress((void**)&wth, g_Wt_hi);
    cudaGetSymbolAddress((void**)&wtl, g_Wt_lo);

    zero_state_k<<<(T_ * H_ + 255) / 256, 256>>>();

    // split conversions
    const int n_emb = MTB * E_;
    split_bf16_k<<<(n_emb + 255) / 256, 256>>>(emb, eh, el, n_emb);
    const int n_w = G4_ * E_;
    split_bf16_k<<<(n_w + 255) / 256, 256>>>(w_ih_f, wh, wl, n_w);
    split_bf16_k<<<(n_w + 255) / 256, 256>>>(w_ih_b, wh + (size_t)n_w, wl + (size_t)n_w, n_w);
    bias_cat_k<<<(G4_ + 255) / 256, 256>>>(b_f, b_b);
    transpose_sq<<<dim3(32, 32), dim3(32, 8)>>>(W_nov, Wt);
    split_bf16_k<<<(H2_ * H2_ + 255) / 256, 256>>>(Wt, wth, wtl, H2_ * H2_);

    // fused pre-projection: g_pre[m][4096] = emb @ [w_ih_f; w_ih_b]^T + [b_f; b_b]
    gemm_mma<<<dim3(G8_ / 128, MTB / 128), 256, GSMEM>>>(eh, el, wh, wl, bias4, pre, E_, G8_);

    // 64 sequential LSTM steps (scan over batch axis)
    for (int s = 0; s < 64; s++) lstm_step<<<128, 256>>>(s, w_hh_f, w_hh_b);

    col_mean_k<<<B_ * H2_ / 256, 256>>>();
    wdot_gemm<<<(B_ * H2_) * 32 / 256, 256>>>(mean, W_fdoc, b_fdoc, doc, H2_, H2_, 1);
    wdot_gemm<<<(B_ * H2_) * 32 / 256, 256>>>(doc, W_sal, nullptr, v, H2_, H2_, 0);
    s0_kernel<<<(B_ * T_) * 32 / 256, 256>>>(w_content, pos_emb, w_abs, biasp);

    // U = sents @ W_nov  (split bf16 tensor path)
    gemm_mma<<<dim3(H2_ / 128, MTB / 128), 256, GSMEM>>>(sh, sl, wth, wtl, nullptr, U, H2_, H2_);

    nov_scan<<<B_, 256>>>(out);
}

// round 6
// speedup vs baseline: 3.0382x; 1.4378x over previous
#include <cuda_runtime.h>
#include <cuda_bf16.h>
#include <cstdint>
#include <cstddef>

// Problem dims
#define T_   256
#define B_   64
#define E_   768
#define H_   512
#define H2_  1024
#define G4_  2048
#define G8_  4096
#define MTB  16384   // T_*B_

// ============================ scratch ============================
__device__ float g_pre[(size_t)MTB * G8_];        // [m][dir*2048 + j*4 + gate]  (interleaved)
__device__ float g_c[2][T_ * H_];
__device__ __nv_bfloat16 g_hh[2][2][T_ * H_];     // h hi  [dir][buf][t*H+k]
__device__ __nv_bfloat16 g_hl[2][2][T_ * H_];     // h lo
__device__ float g_sents[(size_t)MTB * H2_];
__device__ __nv_bfloat16 g_sents_hi[(size_t)MTB * H2_];
__device__ __nv_bfloat16 g_sents_lo[(size_t)MTB * H2_];
__device__ __nv_bfloat16 g_emb_hi[(size_t)MTB * E_];
__device__ __nv_bfloat16 g_emb_lo[(size_t)MTB * E_];
__device__ __nv_bfloat16 g_wih_hi[(size_t)G8_ * E_];   // interleaved rows
__device__ __nv_bfloat16 g_wih_lo[(size_t)G8_ * E_];
__device__ __nv_bfloat16 g_whh_hi[(size_t)G8_ * H_];   // interleaved rows [d*2048 + j*4+g][k]
__device__ __nv_bfloat16 g_whh_lo[(size_t)G8_ * H_];
__device__ float g_bias4[G8_];                         // interleaved
__device__ float g_Wt[H2_ * H2_];
__device__ __nv_bfloat16 g_Wt_hi[H2_ * H2_];
__device__ __nv_bfloat16 g_Wt_lo[H2_ * H2_];
__device__ float g_mean[B_ * H2_];
__device__ float g_doc[B_ * H2_];
__device__ float g_v[B_ * H2_];
__device__ float g_s0[B_ * T_];
__device__ float g_U[(size_t)MTB * H2_];

__device__ __forceinline__ float sigm(float x) { return 1.0f / (1.0f + expf(-x)); }

__device__ __forceinline__ uint32_t smem_u32(const void* p) {
    uint32_t a;
    asm("{ .reg .u64 t; cvta.to.shared.u64 t, %1; cvt.u32.u64 %0, t; }" : "=r"(a) : "l"(p));
    return a;
}
__device__ __forceinline__ uint32_t lds32(uint32_t a) {
    uint32_t v; asm("ld.shared.b32 %0, [%1];" : "=r"(v) : "r"(a)); return v;
}
__device__ __forceinline__ void cp16(uint32_t dst, const void* src) {
    asm volatile("cp.async.cg.shared.global [%0], [%1], 16;" :: "r"(dst), "l"(src));
}
#define CP_COMMIT() asm volatile("cp.async.commit_group;" ::: "memory")
#define CP_WAIT(n)  asm volatile("cp.async.wait_group %0;" :: "n"(n) : "memory")

__device__ __forceinline__ void mma_bf16(float* c, uint32_t a0, uint32_t a1,
                                         uint32_t a2, uint32_t a3,
                                         uint32_t b0, uint32_t b1) {
    asm("mma.sync.aligned.m16n8k16.row.col.f32.bf16.bf16.f32 "
        "{%0,%1,%2,%3}, {%4,%5,%6,%7}, {%8,%9}, {%0,%1,%2,%3};"
        : "+f"(c[0]), "+f"(c[1]), "+f"(c[2]), "+f"(c[3])
        : "r"(a0), "r"(a1), "r"(a2), "r"(a3), "r"(b0), "r"(b1));
}

// ============================ prep kernels ============================
__global__ void zero_state_k() {
    int i = blockIdx.x * blockDim.x + threadIdx.x;
    if (i < T_ * H_) {
        g_c[0][i] = 0.0f; g_c[1][i] = 0.0f;
        __nv_bfloat16 z = __float2bfloat16(0.0f);
        g_hh[0][0][i] = z; g_hh[1][0][i] = z;
        g_hl[0][0][i] = z; g_hl[1][0][i] = z;
    }
}

__global__ void split_bf16_k(const float* __restrict__ src,
                             __nv_bfloat16* __restrict__ hi,
                             __nv_bfloat16* __restrict__ lo, int n) {
    int i = blockIdx.x * 256 + threadIdx.x;
    if (i < n) {
        float x = src[i];
        __nv_bfloat16 h = __float2bfloat16(x);
        hi[i] = h;
        lo[i] = __float2bfloat16(x - __bfloat162float(h));
    }
}

// reorder rows to interleaved gate layout (n' = d*2048 + j*4 + g) and split
__global__ void reorder_split_k(const float* __restrict__ wf, const float* __restrict__ wb,
                                __nv_bfloat16* __restrict__ hi, __nv_bfloat16* __restrict__ lo,
                                int K) {
    int idx = blockIdx.x * 256 + threadIdx.x;
    if (idx >= G8_ * K) return;
    int np = idx / K, k = idx - np * K;
    int d = np >> 11, r = np & 2047;
    int j = r >> 2, g = r & 3;
    const float* w = d ? wb : wf;
    float x = w[(size_t)(g * 512 + j) * K + k];
    __nv_bfloat16 h = __float2bfloat16(x);
    hi[idx] = h;
    lo[idx] = __float2bfloat16(x - __bfloat162float(h));
}

__global__ void bias_cat_k(const float* __restrict__ bf, const float* __restrict__ bb) {
    int np = blockIdx.x * 256 + threadIdx.x;
    if (np < G8_) {
        int d = np >> 11, r = np & 2047;
        int j = r >> 2, g = r & 3;
        g_bias4[np] = (d ? bb : bf)[g * 512 + j];
    }
}

__global__ void transpose_sq(const float* __restrict__ src, float* __restrict__ dst) {
    __shared__ float tile[32][33];
    int x = blockIdx.x * 32 + threadIdx.x;
    int y = blockIdx.y * 32 + threadIdx.y;
#pragma unroll
    for (int j = 0; j < 32; j += 8)
        tile[threadIdx.y + j][threadIdx.x] = src[(size_t)(y + j) * H2_ + x];
    __syncthreads();
    x = blockIdx.y * 32 + threadIdx.x;
    y = blockIdx.x * 32 + threadIdx.y;
#pragma unroll
    for (int j = 0; j < 32; j += 8)
        dst[(size_t)(y + j) * H2_ + x] = tile[threadIdx.x][threadIdx.y + j];
}

// ==================== mma.sync split-bf16 GEMM (3-stage) ====================
#define TROW    80
#define TILE_SZ (128 * TROW)          // 10240 B
#define STAGE_SZ (4 * TILE_SZ)        // 40960 B (Ah, Al, Bh, Bl)
#define GSMEM   (3 * STAGE_SZ)        // 122880 B

__global__ __launch_bounds__(256, 1) void gemm_mma(
    const __nv_bfloat16* __restrict__ Ah, const __nv_bfloat16* __restrict__ Al,
    const __nv_bfloat16* __restrict__ Bh, const __nv_bfloat16* __restrict__ Bl,
    const float* __restrict__ bias, float* __restrict__ C, int K, int N_ld)
{
    extern __shared__ char dsm[];
    const uint32_t sb = smem_u32(dsm);
    const int tid  = threadIdx.x;
    const int wid  = tid >> 5, lane = tid & 31;
    const int t4   = lane >> 2, tm4 = lane & 3;
    const int m0   = blockIdx.y * 128;
    const int n0   = blockIdx.x * 128;
    const int wm   = (wid >> 2) * 64;
    const int wn   = (wid & 3) * 32;

    const char* srcs[4];
    srcs[0] = (const char*)Ah + (size_t)m0 * K * 2;
    srcs[1] = (const char*)Al + (size_t)m0 * K * 2;
    srcs[2] = (const char*)Bh + (size_t)n0 * K * 2;
    srcs[3] = (const char*)Bl + (size_t)n0 * K * 2;
    const size_t rstride = (size_t)K * 2;

    const int prow0 = tid >> 2,         pq0 = tid & 3;
    const int prow1 = (tid + 256) >> 2, pq1 = (tid + 256) & 3;

    const int NC = K >> 5;

#define PREFETCH(c, st) do {                                                    \
    const uint32_t stg = sb + (st) * STAGE_SZ;                                  \
    _Pragma("unroll")                                                           \
    for (int t = 0; t < 4; t++) {                                               \
        cp16(stg + t * TILE_SZ + prow0 * TROW + pq0 * 16,                       \
             srcs[t] + (size_t)prow0 * rstride + (size_t)(c) * 64 + pq0 * 16);  \
        cp16(stg + t * TILE_SZ + prow1 * TROW + pq1 * 16,                       \
             srcs[t] + (size_t)prow1 * rstride + (size_t)(c) * 64 + pq1 * 16);  \
    } } while (0)

    float acc[4][4][4];
#pragma unroll
    for (int mi = 0; mi < 4; mi++)
#pragma unroll
        for (int ni = 0; ni < 4; ni++)
#pragma unroll
            for (int k = 0; k < 4; k++) acc[mi][ni][k] = 0.0f;

    PREFETCH(0, 0); CP_COMMIT();
    if (NC > 1) { PREFETCH(1, 1); CP_COMMIT(); }

    int st = 0;
    for (int c = 0; c < NC; c++) {
        if (c + 1 < NC) { CP_WAIT(1); } else { CP_WAIT(0); }
        __syncthreads();
        if (c + 2 < NC) {
            int nst = st + 2; if (nst >= 3) nst -= 3;
            PREFETCH(c + 2, nst); CP_COMMIT();
        }

        const uint32_t stg = sb + st * STAGE_SZ;
        const uint32_t pAh = stg;
        const uint32_t pAl = stg + TILE_SZ;
        const uint32_t pBh = stg + 2 * TILE_SZ;
        const uint32_t pBl = stg + 3 * TILE_SZ;

#pragma unroll
        for (int ks = 0; ks < 2; ks++) {
            const uint32_t koff = ks * 32 + tm4 * 4;
            uint32_t ah[4][4], al[4][4], bh[4][2], bl[4][2];
#pragma unroll
            for (int mi = 0; mi < 4; mi++) {
                uint32_t base = pAh + (uint32_t)(wm + mi * 16 + t4) * TROW + koff;
                ah[mi][0] = lds32(base);
                ah[mi][1] = lds32(base + 8 * TROW);
                ah[mi][2] = lds32(base + 16);
                ah[mi][3] = lds32(base + 8 * TROW + 16);
            }
#pragma unroll
            for (int ni = 0; ni < 4; ni++) {
                uint32_t base = pBh + (uint32_t)(wn + ni * 8 + t4) * TROW + koff;
                bh[ni][0] = lds32(base);
                bh[ni][1] = lds32(base + 16);
            }
#pragma unroll
            for (int mi = 0; mi < 4; mi++)
#pragma unroll
                for (int ni = 0; ni < 4; ni++)
                    mma_bf16(acc[mi][ni], ah[mi][0], ah[mi][1], ah[mi][2], ah[mi][3],
                             bh[ni][0], bh[ni][1]);
#pragma unroll
            for (int ni = 0; ni < 4; ni++) {
                uint32_t base = pBl + (uint32_t)(wn + ni * 8 + t4) * TROW + koff;
                bl[ni][0] = lds32(base);
                bl[ni][1] = lds32(base + 16);
            }
#pragma unroll
            for (int mi = 0; mi < 4; mi++)
#pragma unroll
                for (int ni = 0; ni < 4; ni++)
                    mma_bf16(acc[mi][ni], ah[mi][0], ah[mi][1], ah[mi][2], ah[mi][3],
                             bl[ni][0], bl[ni][1]);
#pragma unroll
            for (int mi = 0; mi < 4; mi++) {
                uint32_t base = pAl + (uint32_t)(wm + mi * 16 + t4) * TROW + koff;
                al[mi][0] = lds32(base);
                al[mi][1] = lds32(base + 8 * TROW);
                al[mi][2] = lds32(base + 16);
                al[mi][3] = lds32(base + 8 * TROW + 16);
            }
#pragma unroll
            for (int mi = 0; mi < 4; mi++)
#pragma unroll
                for (int ni = 0; ni < 4; ni++)
                    mma_bf16(acc[mi][ni], al[mi][0], al[mi][1], al[mi][2], al[mi][3],
                             bh[ni][0], bh[ni][1]);
        }
        if (++st == 3) st = 0;
    }
#undef PREFETCH

#pragma unroll
    for (int mi = 0; mi < 4; mi++) {
        const int r0 = m0 + wm + mi * 16 + t4;
#pragma unroll
        for (int ni = 0; ni < 4; ni++) {
            const int col = n0 + wn + ni * 8 + 2 * tm4;
            float b0 = bias ? bias[col] : 0.0f;
            float b1 = bias ? bias[col + 1] : 0.0f;
            float2 v0 = { acc[mi][ni][0] + b0, acc[mi][ni][1] + b1 };
            float2 v1 = { acc[mi][ni][2] + b0, acc[mi][ni][3] + b1 };
            *(float2*)(C + (size_t)r0 * N_ld + col)       = v0;
            *(float2*)(C + (size_t)(r0 + 8) * N_ld + col) = v1;
        }
    }
}

// ==================== LSTM step via mma.sync (split bf16) ====================
// Per step s: C[t][n] = h_in[t] @ Whh[n]^T  (n = j*4+gate interleaved), per dir.
// Tile: M=128 (t), N=64 (16 j x 4 gates), K=512. Grid (32 n, 2 m, 2 dir).
// Epilogue: lane-pair shfl gathers all 4 gates per (t,j); fused cell update;
// writes c, h hi/lo (next buf), sents fp32/hi/lo.
#define LTROW    80
#define LA_SZ   (128 * LTROW)         // 10240
#define LB_SZ   (64 * LTROW)          // 5120
#define LSTAGE  (2 * LA_SZ + 2 * LB_SZ)  // 30720
#define LSMEM   (3 * LSTAGE)             // 92160

__global__ __launch_bounds__(256, 1) void lstm_mma(int s) {
    extern __shared__ char dsm[];
    const uint32_t sb = smem_u32(dsm);
    const int tid  = threadIdx.x;
    const int wid  = tid >> 5, lane = tid & 31;
    const int t4   = lane >> 2, tm4 = lane & 3;
    const int n0   = blockIdx.x * 64;
    const int m0   = blockIdx.y * 128;
    const int d    = blockIdx.z;
    const int wm   = (wid >> 2) * 64;
    const int wn   = (wid & 3) * 16;

    const __nv_bfloat16* Ahp = g_hh[d][s & 1];
    const __nv_bfloat16* Alp = g_hl[d][s & 1];
    const char* srcA[2] = { (const char*)(Ahp + (size_t)m0 * H_),
                            (const char*)(Alp + (size_t)m0 * H_) };
    const char* srcB[2] = { (const char*)(g_whh_hi + (size_t)(d * G4_ + n0) * H_),
                            (const char*)(g_whh_lo + (size_t)(d * G4_ + n0) * H_) };
    const size_t rstride = (size_t)H_ * 2;   // 1024 B

    const int arow0 = tid >> 2,         aq0 = tid & 3;
    const int arow1 = (tid + 256) >> 2, aq1 = (tid + 256) & 3;
    const int brow  = tid >> 2,         bq  = tid & 3;   // rows 0..63

    const int NC = H_ >> 5;   // 16

#define LPREF(c, st) do {                                                       \
    const uint32_t stg = sb + (st) * LSTAGE;                                    \
    _Pragma("unroll")                                                           \
    for (int t = 0; t < 2; t++) {                                               \
        cp16(stg + t * LA_SZ + arow0 * LTROW + aq0 * 16,                        \
             srcA[t] + (size_t)arow0 * rstride + (size_t)(c) * 64 + aq0 * 16);  \
        cp16(stg + t * LA_SZ + arow1 * LTROW + aq1 * 16,                        \
             srcA[t] + (size_t)arow1 * rstride + (size_t)(c) * 64 + aq1 * 16);  \
        cp16(stg + 2 * LA_SZ + t * LB_SZ + brow * LTROW + bq * 16,              \
             srcB[t] + (size_t)brow * rstride + (size_t)(c) * 64 + bq * 16);    \
    } } while (0)

    float acc[4][2][4];
#pragma unroll
    for (int mi = 0; mi < 4; mi++)
#pragma unroll
        for (int ni = 0; ni < 2; ni++)
#pragma unroll
            for (int k = 0; k < 4; k++) acc[mi][ni][k] = 0.0f;

    LPREF(0, 0); CP_COMMIT();
    LPREF(1, 1); CP_COMMIT();

    int st = 0;
    for (int c = 0; c < NC; c++) {
        if (c + 1 < NC) { CP_WAIT(1); } else { CP_WAIT(0); }
        __syncthreads();
        if (c + 2 < NC) {
            int nst = st + 2; if (nst >= 3) nst -= 3;
            LPREF(c + 2, nst); CP_COMMIT();
        }

        const uint32_t stg = sb + st * LSTAGE;
        const uint32_t pAh = stg;
        const uint32_t pAl = stg + LA_SZ;
        const uint32_t pBh = stg + 2 * LA_SZ;
        const uint32_t pBl = stg + 2 * LA_SZ + LB_SZ;

#pragma unroll
        for (int ks = 0; ks < 2; ks++) {
            const uint32_t koff = ks * 32 + tm4 * 4;
            uint32_t ah[4][4], al[4][4], bh[2][2], bl[2][2];
#pragma unroll
            for (int mi = 0; mi < 4; mi++) {
                uint32_t base = pAh + (uint32_t)(wm + mi * 16 + t4) * LTROW + koff;
                ah[mi][0] = lds32(base);
                ah[mi][1] = lds32(base + 8 * LTROW);
                ah[mi][2] = lds32(base + 16);
                ah[mi][3] = lds32(base + 8 * LTROW + 16);
            }
#pragma unroll
            for (int ni = 0; ni < 2; ni++) {
                uint32_t base = pBh + (uint32_t)(wn + ni * 8 + t4) * LTROW + koff;
                bh[ni][0] = lds32(base);
                bh[ni][1] = lds32(base + 16);
            }
#pragma unroll
            for (int mi = 0; mi < 4; mi++)
#pragma unroll
                for (int ni = 0; ni < 2; ni++)
                    mma_bf16(acc[mi][ni], ah[mi][0], ah[mi][1], ah[mi][2], ah[mi][3],
                             bh[ni][0], bh[ni][1]);
#pragma unroll
            for (int ni = 0; ni < 2; ni++) {
                uint32_t base = pBl + (uint32_t)(wn + ni * 8 + t4) * LTROW + koff;
                bl[ni][0] = lds32(base);
                bl[ni][1] = lds32(base + 16);
            }
#pragma unroll
            for (int mi = 0; mi < 4; mi++)
#pragma unroll
                for (int ni = 0; ni < 2; ni++)
                    mma_bf16(acc[mi][ni], ah[mi][0], ah[mi][1], ah[mi][2], ah[mi][3],
                             bl[ni][0], bl[ni][1]);
#pragma unroll
            for (int mi = 0; mi < 4; mi++) {
                uint32_t base = pAl + (uint32_t)(wm + mi * 16 + t4) * LTROW + koff;
                al[mi][0] = lds32(base);
                al[mi][1] = lds32(base + 8 * LTROW);
                al[mi][2] = lds32(base + 16);
                al[mi][3] = lds32(base + 8 * LTROW + 16);
            }
#pragma unroll
            for (int mi = 0; mi < 4; mi++)
#pragma unroll
                for (int ni = 0; ni < 2; ni++)
                    mma_bf16(acc[mi][ni], al[mi][0], al[mi][1], al[mi][2], al[mi][3],
                             bh[ni][0], bh[ni][1]);
        }
        if (++st == 3) st = 0;
    }
#undef LPREF

    // ---- epilogue: gather 4 gates per (t,j) via lane-pair shfl, LSTM cell ----
    const int bb = d ? (63 - s) : s;
    float* Cst = g_c[d];
    __nv_bfloat16* Hh = g_hh[d][(s & 1) ^ 1];
    __nv_bfloat16* Hl = g_hl[d][(s & 1) ^ 1];
    const int odd = tm4 & 1;

#pragma unroll
    for (int mi = 0; mi < 4; mi++) {
        const int r0 = m0 + wm + mi * 16 + t4;
#pragma unroll
        for (int ni = 0; ni < 2; ni++) {
            float* a = acc[mi][ni];
            const int c0 = n0 + wn + ni * 8 + 2 * tm4;   // local col (dir-relative)
            // exchange: even lane keeps row r0 (has i,f; needs g,o from odd)
            //           odd  lane keeps row r0+8 (has g,o; needs i,f from even)
            float y0 = __shfl_xor_sync(0xffffffffu, odd ? a[0] : a[2], 1);
            float y1 = __shfl_xor_sync(0xffffffffu, odd ? a[1] : a[3], 1);
            const int t = odd ? (r0 + 8) : r0;
            float gi, gf, gg, go;
            if (!odd) { gi = a[0]; gf = a[1]; gg = y0;  go = y1;  }
            else      { gi = y0;  gf = y1;  gg = a[2]; go = a[3]; }
            const int j = c0 >> 2;
            const float4 p = *(const float4*)(g_pre + (size_t)(t * B_ + bb) * G8_
                                              + d * G4_ + j * 4);
            gi += p.x; gf += p.y; gg += p.z; go += p.w;
            float cprev = Cst[t * H_ + j];
            float cnew  = sigm(gf) * cprev + sigm(gi) * tanhf(gg);
            float hnew  = sigm(go) * tanhf(cnew);
            Cst[t * H_ + j] = cnew;
            __nv_bfloat16 hh = __float2bfloat16(hnew);
            __nv_bfloat16 hl = __float2bfloat16(hnew - __bfloat162float(hh));
            Hh[t * H_ + j] = hh;
            Hl[t * H_ + j] = hl;
            const size_t si = ((size_t)t * B_ + bb) * (size_t)H2_ + (size_t)d * H_ + j;
            g_sents[si]    = hnew;
            g_sents_hi[si] = hh;
            g_sents_lo[si] = hl;
        }
    }
}

// ==================== small kernels ====================
__global__ void col_mean_k() {
    int idx = blockIdx.x * 256 + threadIdx.x;
    float sum = 0.0f;
    for (int t = 0; t < T_; t++) sum += g_sents[(size_t)t * (B_ * H2_) + idx];
    g_mean[idx] = sum * (1.0f / 256.0f);
}

__global__ void wdot_gemm(const float* __restrict__ X, const float* __restrict__ W,
                          const float* __restrict__ bias, float* __restrict__ out,
                          int N, int K, int act)
{
    int gw   = (blockIdx.x * blockDim.x + threadIdx.x) >> 5;
    int lane = threadIdx.x & 31;
    int b = gw / N, n = gw % N;
    const float* xr = X + (size_t)b * K;
    const float* wr = W + (size_t)n * K;
    float s = 0.0f;
    for (int k = lane * 4; k < K; k += 128) {
        float4 xv = *(const float4*)(xr + k);
        float4 wv = *(const float4*)(wr + k);
        s += xv.x * wv.x + xv.y * wv.y + xv.z * wv.z + xv.w * wv.w;
    }
#pragma unroll
    for (int off = 16; off; off >>= 1) s += __shfl_xor_sync(0xffffffffu, s, off);
    if (lane == 0) {
        float rr = s + (bias ? bias[n] : 0.0f);
        if (act) rr = tanhf(rr);
        out[(size_t)b * N + n] = rr;
    }
}

__global__ void s0_kernel(const float* __restrict__ w_content,
                          const float* __restrict__ pos_emb,
                          const float* __restrict__ w_abs,
                          const float* __restrict__ biasp)
{
    int gw   = (blockIdx.x * blockDim.x + threadIdx.x) >> 5;
    int lane = threadIdx.x & 31;
    int b = gw >> 8, t = gw & 255;
    const float* hr = g_sents + ((size_t)t * B_ + b) * (size_t)H2_;
    const float* vr = g_v + (size_t)b * H2_;
    float s = 0.0f;
    for (int k = lane * 4; k < H2_; k += 128) {
        float4 hv = *(const float4*)(hr + k);
        float4 wc = *(const float4*)(w_content + k);
        float4 vv = *(const float4*)(vr + k);
        s += hv.x * (wc.x + vv.x) + hv.y * (wc.y + vv.y)
           + hv.z * (wc.z + vv.z) + hv.w * (wc.w + vv.w);
    }
    for (int p = lane; p < 100; p += 32) s += pos_emb[t * 100 + p] * w_abs[p];
#pragma unroll
    for (int off = 16; off; off >>= 1) s += __shfl_xor_sync(0xffffffffu, s, off);
    if (lane == 0) g_s0[b * T_ + t] = s + biasp[0];
}

__global__ __launch_bounds__(256) void nov_scan(float* __restrict__ out) {
    __shared__ float summ[H2_];
    __shared__ float red[8];
    __shared__ float prsh;
    const int b = blockIdx.x, tid = threadIdx.x;
    const int lane = tid & 31, wid = tid >> 5;
#pragma unroll
    for (int i = 0; i < 4; i++) summ[tid + i * 256] = 0.0f;
    __syncthreads();
    for (int t = 0; t < T_; t++) {
        const float* Ur = g_U + ((size_t)t * B_ + b) * (size_t)H2_;
        float p = 0.0f;
#pragma unroll
        for (int i = 0; i < 4; i++) {
            int k = tid + i * 256;
            p += Ur[k] * tanhf(summ[k]);
        }
#pragma unroll
        for (int off = 16; off; off >>= 1) p += __shfl_xor_sync(0xffffffffu, p, off);
        if (lane == 0) red[wid] = p;
        __syncthreads();
        if (tid == 0) {
            float nov = red[0] + red[1] + red[2] + red[3]
                      + red[4] + red[5] + red[6] + red[7];
            float pr = 1.0f / (1.0f + expf(-(g_s0[b * T_ + t] - nov)));
            prsh = pr;
            out[b * T_ + t] = pr;
        }
        __syncthreads();
        float pr = prsh;
        const float* hr = g_sents + ((size_t)t * B_ + b) * (size_t)H2_;
#pragma unroll
        for (int i = 0; i < 4; i++) {
            int k = tid + i * 256;
            summ[k] += pr * hr[k];
        }
        __syncthreads();
    }
}

// ==================== host ====================
extern "C" void kernel_launch(void* const* d_in, const int* in_sizes, int n_in,
                              void* d_out, int out_size) {
    (void)in_sizes; (void)n_in; (void)out_size;
    const float* emb       = (const float*)d_in[0];
    const float* w_ih_f    = (const float*)d_in[2];
    const float* w_hh_f    = (const float*)d_in[3];
    const float* b_f       = (const float*)d_in[4];
    const float* w_ih_b    = (const float*)d_in[5];
    const float* w_hh_b    = (const float*)d_in[6];
    const float* b_b       = (const float*)d_in[7];
    const float* W_fdoc    = (const float*)d_in[8];
    const float* b_fdoc    = (const float*)d_in[9];
    const float* pos_emb   = (const float*)d_in[10];
    const float* w_content = (const float*)d_in[11];
    const float* W_sal     = (const float*)d_in[12];
    const float* W_nov     = (const float*)d_in[13];
    const float* w_abs     = (const float*)d_in[14];
    const float* biasp     = (const float*)d_in[15];
    float* out = (float*)d_out;

    static int smem_set = 0;
    if (!smem_set) {
        cudaFuncSetAttribute(gemm_mma, cudaFuncAttributeMaxDynamicSharedMemorySize, GSMEM);
        cudaFuncSetAttribute(lstm_mma, cudaFuncAttributeMaxDynamicSharedMemorySize, LSMEM);
        smem_set = 1;
    }

    float *pre, *mean, *doc, *v, *Wt, *U, *bias4;
    __nv_bfloat16 *eh, *el, *wh, *wl, *whh_h, *whh_l, *sh, *sl, *wth, *wtl;
    cudaGetSymbolAddress((void**)&pre,   g_pre);
    cudaGetSymbolAddress((void**)&mean,  g_mean);
    cudaGetSymbolAddress((void**)&doc,   g_doc);
    cudaGetSymbolAddress((void**)&v,     g_v);
    cudaGetSymbolAddress((void**)&Wt,    g_Wt);
    cudaGetSymbolAddress((void**)&U,     g_U);
    cudaGetSymbolAddress((void**)&bias4, g_bias4);
    cudaGetSymbolAddress((void**)&eh,    g_emb_hi);
    cudaGetSymbolAddress((void**)&el,    g_emb_lo);
    cudaGetSymbolAddress((void**)&wh,    g_wih_hi);
    cudaGetSymbolAddress((void**)&wl,    g_wih_lo);
    cudaGetSymbolAddress((void**)&whh_h, g_whh_hi);
    cudaGetSymbolAddress((void**)&whh_l, g_whh_lo);
    cudaGetSymbolAddress((void**)&sh,    g_sents_hi);
    cudaGetSymbolAddress((void**)&sl,    g_sents_lo);
    cudaGetSymbolAddress((void**)&wth,   g_Wt_hi);
    cudaGetSymbolAddress((void**)&wtl,   g_Wt_lo);

    zero_state_k<<<(T_ * H_ + 255) / 256, 256>>>();

    // conversions / reorders
    const int n_emb = MTB * E_;
    split_bf16_k<<<(n_emb + 255) / 256, 256>>>(emb, eh, el, n_emb);
    reorder_split_k<<<(G8_ * E_ + 255) / 256, 256>>>(w_ih_f, w_ih_b, wh, wl, E_);
    reorder_split_k<<<(G8_ * H_ + 255) / 256, 256>>>(w_hh_f, w_hh_b, whh_h, whh_l, H_);
    bias_cat_k<<<(G8_ + 255) / 256, 256>>>(b_f, b_b);
    transpose_sq<<<dim3(32, 32), dim3(32, 8)>>>(W_nov, Wt);
    split_bf16_k<<<(H2_ * H2_ + 255) / 256, 256>>>(Wt, wth, wtl, H2_ * H2_);

    // pre-projection (gate-interleaved N): g_pre = emb @ W4^T + bias4
    gemm_mma<<<dim3(G8_ / 128, MTB / 128), 256, GSMEM>>>(eh, el, wh, wl, bias4, pre, E_, G8_);

    // 64 sequential LSTM steps on tensor cores
    for (int s = 0; s < 64; s++)
        lstm_mma<<<dim3(32, 2, 2), 256, LSMEM>>>(s);

    col_mean_k<<<B_ * H2_ / 256, 256>>>();
    wdot_gemm<<<(B_ * H2_) * 32 / 256, 256>>>(mean, W_fdoc, b_fdoc, doc, H2_, H2_, 1);
    wdot_gemm<<<(B_ * H2_) * 32 / 256, 256>>>(doc, W_sal, nullptr, v, H2_, H2_, 0);
    s0_kernel<<<(B_ * T_) * 32 / 256, 256>>>(w_content, pos_emb, w_abs, biasp);

    // U = sents @ W_nov (split bf16 tensor path)
    gemm_mma<<<dim3(H2_ / 128, MTB / 128), 256, GSMEM>>>(sh, sl, wth, wtl, nullptr, U, H2_, H2_);

    nov_scan<<<B_, 256>>>(out);
}